// round 3
// baseline (speedup 1.0000x reference)
#include <cuda_runtime.h>
#include <stdint.h>

#define N_NODES 10000
#define ROW_WORDS 320      // 313 words used (10016 bits), padded to 320 for alignment
#define USED_WORDS 313
#define D 256
#define MAX_NBR 1024

// Scratch (allocation-free rule: __device__ globals)
__device__ uint32_t g_bitmap[(size_t)N_NODES * ROW_WORDS];   // 12.8 MB
__device__ float    g_dinv[N_NODES];
__device__ float    g_h[(size_t)N_NODES * D];                // 10.24 MB

// ---------------------------------------------------------------- zero bitmap
__global__ void zero_bitmap_kernel() {
    const size_t total = (size_t)N_NODES * ROW_WORDS / 4;   // uint4 count
    uint4* p = (uint4*)g_bitmap;
    uint4 z = make_uint4(0u, 0u, 0u, 0u);
    for (size_t i = (size_t)blockIdx.x * blockDim.x + threadIdx.x; i < total;
         i += (size_t)gridDim.x * blockDim.x)
        p[i] = z;
}

// ------------------------------------------------------------- edge scatter
// edge_index is int32 [2, E] (JAX downcasts int64->int32 without x64 mode).
__global__ void scatter_kernel(const int* __restrict__ ei, int E) {
    int e = blockIdx.x * blockDim.x + threadIdx.x;
    if (e >= E) return;
    int s = ei[e];
    int d = ei[E + e];
    if ((unsigned)s >= N_NODES || (unsigned)d >= N_NODES) return;  // defensive
    atomicOr(&g_bitmap[(size_t)s * ROW_WORDS + (d >> 5)], 1u << (d & 31));
    atomicOr(&g_bitmap[(size_t)d * ROW_WORDS + (s >> 5)], 1u << (s & 31));
}

// ------------------------------------------------------ degree -> dinv
__global__ void degree_kernel() {
    int i = blockIdx.x * (blockDim.x >> 5) + (threadIdx.x >> 5);
    if (i >= N_NODES) return;
    int lane = threadIdx.x & 31;
    const uint32_t* row = g_bitmap + (size_t)i * ROW_WORDS;
    int s = 0;
    for (int w = lane; w < USED_WORDS; w += 32) s += __popc(row[w]);
    #pragma unroll
    for (int o = 16; o; o >>= 1) s += __shfl_down_sync(0xffffffffu, s, o);
    if (lane == 0) g_dinv[i] = rsqrtf((float)s + 1.0f);
}

// ------------------------------------------------------ SpMM: h = A_norm @ x
// One CTA (256 threads) per row. Deterministic neighbor-list construction
// (count -> block exclusive scan -> ordered write), then column-parallel gather.
__global__ __launch_bounds__(256) void spmm_kernel(const float* __restrict__ x) {
    const int i = blockIdx.x;
    const int t = threadIdx.x;
    __shared__ int   s_nbr[MAX_NBR];
    __shared__ float s_coef[MAX_NBR];
    __shared__ int   s_warp_tot[8];
    __shared__ int   s_cnt;

    const uint32_t* row = g_bitmap + (size_t)i * ROW_WORDS;

    // thread t owns words {t, t+256} (t+256 only if t<64); padding words are zero
    uint32_t w0 = row[t];
    uint32_t w1 = (t < ROW_WORDS - 256) ? row[t + 256] : 0u;
    int cnt_local = __popc(w0) + __popc(w1);

    // block exclusive scan of cnt_local (deterministic ordering)
    int lane = t & 31, wid = t >> 5;
    int v = cnt_local;
    #pragma unroll
    for (int o = 1; o < 32; o <<= 1) {
        int u = __shfl_up_sync(0xffffffffu, v, o);
        if (lane >= o) v += u;
    }
    if (lane == 31) s_warp_tot[wid] = v;
    __syncthreads();
    int base = 0;
    for (int ww = 0; ww < wid; ww++) base += s_warp_tot[ww];
    int offset = base + v - cnt_local;   // exclusive prefix for this thread
    if (t == 0) {
        int tot = 0;
        #pragma unroll
        for (int ww = 0; ww < 8; ww++) tot += s_warp_tot[ww];
        s_cnt = tot;
    }
    // write this thread's bits (word t first, then word t+256)
    {
        uint32_t bits = w0;
        int wbase = t * 32;
        while (bits) {
            int b = __ffs(bits) - 1;
            bits &= bits - 1;
            if (offset < MAX_NBR) s_nbr[offset] = wbase + b;
            offset++;
        }
        bits = w1;
        wbase = (t + 256) * 32;
        while (bits) {
            int b = __ffs(bits) - 1;
            bits &= bits - 1;
            if (offset < MAX_NBR) s_nbr[offset] = wbase + b;
            offset++;
        }
    }
    __syncthreads();
    int cnt = min(s_cnt, MAX_NBR);
    for (int k = t; k < cnt; k += 256) s_coef[k] = g_dinv[s_nbr[k]];
    __syncthreads();

    const float di = g_dinv[i];
    const int d = t;                      // one column per thread
    float acc = di * x[(size_t)i * D + d];   // identity (self-loop) term
    int k = 0;
    for (; k + 4 <= cnt; k += 4) {
        int   j0 = s_nbr[k],     j1 = s_nbr[k + 1], j2 = s_nbr[k + 2], j3 = s_nbr[k + 3];
        float c0 = s_coef[k],    c1 = s_coef[k + 1], c2 = s_coef[k + 2], c3 = s_coef[k + 3];
        float x0 = x[(size_t)j0 * D + d];
        float x1 = x[(size_t)j1 * D + d];
        float x2 = x[(size_t)j2 * D + d];
        float x3 = x[(size_t)j3 * D + d];
        acc += c0 * x0;
        acc += c1 * x1;
        acc += c2 * x2;
        acc += c3 * x3;
    }
    for (; k < cnt; k++) acc += s_coef[k] * x[(size_t)s_nbr[k] * D + d];
    g_h[(size_t)i * D + d] = di * acc;
}

// ------------------------------------------------------ GEMM: out = h @ W
// 64x64 tile, BK=16, 256 threads, 4x4 microtile, float4 smem paths.
__global__ __launch_bounds__(256) void gemm_kernel(const float* __restrict__ W,
                                                   float* __restrict__ C) {
    const float* A = g_h;
    const int n0 = blockIdx.x * 64;
    const int m0 = blockIdx.y * 64;
    __shared__ float As[16][64];   // As[k][m]
    __shared__ float Bs[16][64];   // Bs[k][n]
    const int t = threadIdx.x;
    const int tx = t & 15, ty = t >> 4;

    float acc[4][4];
    #pragma unroll
    for (int r = 0; r < 4; r++)
        #pragma unroll
        for (int c = 0; c < 4; c++) acc[r][c] = 0.f;

    const int am = t >> 2, akq = (t & 3) * 4;      // A loader coords
    const int bk = t >> 4, bnq = (t & 15) * 4;     // B loader coords

    for (int k0 = 0; k0 < 256; k0 += 16) {
        float4 av = make_float4(0.f, 0.f, 0.f, 0.f);
        int arow = m0 + am;
        if (arow < N_NODES)
            av = *(const float4*)&A[(size_t)arow * 256 + k0 + akq];
        As[akq + 0][am] = av.x;
        As[akq + 1][am] = av.y;
        As[akq + 2][am] = av.z;
        As[akq + 3][am] = av.w;
        *(float4*)&Bs[bk][bnq] = *(const float4*)&W[(size_t)(k0 + bk) * 256 + n0 + bnq];
        __syncthreads();
        #pragma unroll
        for (int kk = 0; kk < 16; kk++) {
            float4 a = *(const float4*)&As[kk][ty * 4];
            float4 b = *(const float4*)&Bs[kk][tx * 4];
            acc[0][0] += a.x * b.x; acc[0][1] += a.x * b.y; acc[0][2] += a.x * b.z; acc[0][3] += a.x * b.w;
            acc[1][0] += a.y * b.x; acc[1][1] += a.y * b.y; acc[1][2] += a.y * b.z; acc[1][3] += a.y * b.w;
            acc[2][0] += a.z * b.x; acc[2][1] += a.z * b.y; acc[2][2] += a.z * b.z; acc[2][3] += a.z * b.w;
            acc[3][0] += a.w * b.x; acc[3][1] += a.w * b.y; acc[3][2] += a.w * b.z; acc[3][3] += a.w * b.w;
        }
        __syncthreads();
    }
    #pragma unroll
    for (int r = 0; r < 4; r++) {
        int m = m0 + ty * 4 + r;
        if (m < N_NODES)
            *(float4*)&C[(size_t)m * 256 + n0 + tx * 4] =
                make_float4(acc[r][0], acc[r][1], acc[r][2], acc[r][3]);
    }
}

// ---------------------------------------------------------------- launch
extern "C" void kernel_launch(void* const* d_in, const int* in_sizes, int n_in,
                              void* d_out, int out_size) {
    const float* x   = (const float*)d_in[0];
    const int*   ei  = (const int*)d_in[1];
    const float* w   = (const float*)d_in[2];
    float*       out = (float*)d_out;
    const int E = in_sizes[1] / 2;

    zero_bitmap_kernel<<<1024, 256>>>();
    scatter_kernel<<<(E + 255) / 256, 256>>>(ei, E);
    degree_kernel<<<(N_NODES + 7) / 8, 256>>>();
    spmm_kernel<<<N_NODES, 256>>>(x);
    gemm_kernel<<<dim3(256 / 64, (N_NODES + 63) / 64), 256>>>(w, out);
}

// round 5
// speedup vs baseline: 1.1636x; 1.1636x over previous
#include <cuda_runtime.h>
#include <stdint.h>

#define N_NODES 10000
#define ROW_WORDS 320      // 313 words used (10016 bits), padded to 320 for alignment
#define USED_WORDS 313
#define D 256
#define MAX_NBR 1024

// Scratch (allocation-free rule: __device__ globals)
__device__ uint32_t g_bitmap[(size_t)N_NODES * ROW_WORDS];   // 12.8 MB
__device__ float    g_dinv[N_NODES];
__device__ float    g_xw[(size_t)N_NODES * D];               // dinv[j] * (x[j] @ W)

// ---------------------------------------------------------------- zero bitmap
__global__ void zero_bitmap_kernel() {
    const size_t total = (size_t)N_NODES * ROW_WORDS / 4;   // uint4 count
    uint4* p = (uint4*)g_bitmap;
    uint4 z = make_uint4(0u, 0u, 0u, 0u);
    for (size_t i = (size_t)blockIdx.x * blockDim.x + threadIdx.x; i < total;
         i += (size_t)gridDim.x * blockDim.x)
        p[i] = z;
}

// ------------------------------------------------------------- edge scatter
// edge_index is int32 [2, E].
__global__ void scatter_kernel(const int* __restrict__ ei, int E) {
    int e = blockIdx.x * blockDim.x + threadIdx.x;
    if (e >= E) return;
    int s = ei[e];
    int d = ei[E + e];
    if ((unsigned)s >= N_NODES || (unsigned)d >= N_NODES) return;  // defensive
    atomicOr(&g_bitmap[(size_t)s * ROW_WORDS + (d >> 5)], 1u << (d & 31));
    atomicOr(&g_bitmap[(size_t)d * ROW_WORDS + (s >> 5)], 1u << (s & 31));
}

// ------------------------------------------------------ degree -> dinv
__global__ void degree_kernel() {
    int i = blockIdx.x * (blockDim.x >> 5) + (threadIdx.x >> 5);
    if (i >= N_NODES) return;
    int lane = threadIdx.x & 31;
    const uint32_t* row = g_bitmap + (size_t)i * ROW_WORDS;
    int s = 0;
    for (int w = lane; w < USED_WORDS; w += 32) s += __popc(row[w]);
    #pragma unroll
    for (int o = 16; o; o >>= 1) s += __shfl_down_sync(0xffffffffu, s, o);
    if (lane == 0) g_dinv[i] = rsqrtf((float)s + 1.0f);
}

// ------------------------------------------------------ GEMM: xw = dinv .* (x @ W)
// 64x64 tile, BK=16, 256 threads, 4x4 microtile, float4 smem paths.
// Epilogue scales each output row m by dinv[m].
__global__ __launch_bounds__(256) void gemm_kernel(const float* __restrict__ A,
                                                   const float* __restrict__ W) {
    const int n0 = blockIdx.x * 64;
    const int m0 = blockIdx.y * 64;
    __shared__ float As[16][64];   // As[k][m]
    __shared__ float Bs[16][64];   // Bs[k][n]
    const int t = threadIdx.x;
    const int tx = t & 15, ty = t >> 4;

    float acc[4][4];
    #pragma unroll
    for (int r = 0; r < 4; r++)
        #pragma unroll
        for (int c = 0; c < 4; c++) acc[r][c] = 0.f;

    const int am = t >> 2, akq = (t & 3) * 4;      // A loader coords
    const int bk = t >> 4, bnq = (t & 15) * 4;     // B loader coords

    for (int k0 = 0; k0 < 256; k0 += 16) {
        float4 av = make_float4(0.f, 0.f, 0.f, 0.f);
        int arow = m0 + am;
        if (arow < N_NODES)
            av = *(const float4*)&A[(size_t)arow * 256 + k0 + akq];
        As[akq + 0][am] = av.x;
        As[akq + 1][am] = av.y;
        As[akq + 2][am] = av.z;
        As[akq + 3][am] = av.w;
        *(float4*)&Bs[bk][bnq] = *(const float4*)&W[(size_t)(k0 + bk) * 256 + n0 + bnq];
        __syncthreads();
        #pragma unroll
        for (int kk = 0; kk < 16; kk++) {
            float4 a = *(const float4*)&As[kk][ty * 4];
            float4 b = *(const float4*)&Bs[kk][tx * 4];
            acc[0][0] += a.x * b.x; acc[0][1] += a.x * b.y; acc[0][2] += a.x * b.z; acc[0][3] += a.x * b.w;
            acc[1][0] += a.y * b.x; acc[1][1] += a.y * b.y; acc[1][2] += a.y * b.z; acc[1][3] += a.y * b.w;
            acc[2][0] += a.z * b.x; acc[2][1] += a.z * b.y; acc[2][2] += a.z * b.z; acc[2][3] += a.z * b.w;
            acc[3][0] += a.w * b.x; acc[3][1] += a.w * b.y; acc[3][2] += a.w * b.z; acc[3][3] += a.w * b.w;
        }
        __syncthreads();
    }
    #pragma unroll
    for (int r = 0; r < 4; r++) {
        int m = m0 + ty * 4 + r;
        if (m < N_NODES) {
            float dv = g_dinv[m];
            *(float4*)&g_xw[(size_t)m * 256 + n0 + tx * 4] =
                make_float4(dv * acc[r][0], dv * acc[r][1],
                            dv * acc[r][2], dv * acc[r][3]);
        }
    }
}

// ------------------------------------------------------ SpMM: out = A_norm @ xw'
// One CTA (256 threads) per row i.
// Phase 1: deterministic neighbor extraction (count -> scan -> ordered write of
//          precomputed BYTE offsets j*1024).
// Phase 2: vectorized gather-sum. Thread layout: c = t&63 owns columns
//          [4c,4c+4) as a float4; s = t>>6 handles neighbors k ≡ s (mod 4).
//          Fixed-order shared reduction over the 4 slices -> deterministic.
__global__ __launch_bounds__(256) void spmm_kernel(float* __restrict__ out) {
    const int i = blockIdx.x;
    const int t = threadIdx.x;
    __shared__ int    s_off[MAX_NBR];     // byte offsets (j << 10)
    __shared__ int    s_warp_tot[8];
    __shared__ int    s_cnt;
    __shared__ float4 s_red[4][64];

    const uint32_t* row = g_bitmap + (size_t)i * ROW_WORDS;

    // thread t owns words {t, t+256} (t+256 only if t<64); padding words are zero
    uint32_t w0 = row[t];
    uint32_t w1 = (t < ROW_WORDS - 256) ? row[t + 256] : 0u;
    int cnt_local = __popc(w0) + __popc(w1);

    // block exclusive scan of cnt_local (deterministic ordering)
    int lane = t & 31, wid = t >> 5;
    int v = cnt_local;
    #pragma unroll
    for (int o = 1; o < 32; o <<= 1) {
        int u = __shfl_up_sync(0xffffffffu, v, o);
        if (lane >= o) v += u;
    }
    if (lane == 31) s_warp_tot[wid] = v;
    __syncthreads();
    int base = 0;
    for (int ww = 0; ww < wid; ww++) base += s_warp_tot[ww];
    int offset = base + v - cnt_local;   // exclusive prefix for this thread
    if (t == 0) {
        int tot = 0;
        #pragma unroll
        for (int ww = 0; ww < 8; ww++) tot += s_warp_tot[ww];
        s_cnt = tot;
    }
    // write this thread's bits as byte offsets (word t first, then word t+256)
    {
        uint32_t bits = w0;
        int wbase = t * 32;
        while (bits) {
            int b = __ffs(bits) - 1;
            bits &= bits - 1;
            if (offset < MAX_NBR) s_off[offset] = (wbase + b) << 10;
            offset++;
        }
        bits = w1;
        wbase = (t + 256) * 32;
        while (bits) {
            int b = __ffs(bits) - 1;
            bits &= bits - 1;
            if (offset < MAX_NBR) s_off[offset] = (wbase + b) << 10;
            offset++;
        }
    }
    __syncthreads();
    const int cnt = min(s_cnt, MAX_NBR);

    const int c = t & 63;        // column group: float4 at cols [4c, 4c+4)
    const int s = t >> 6;        // neighbor slice
    const char* xwb = (const char*)g_xw + (size_t)c * 16;

    float4 acc = make_float4(0.f, 0.f, 0.f, 0.f);
    if (s == 0) {
        // +I self term: xw row i (already dinv[i]-scaled)
        acc = *(const float4*)(xwb + ((size_t)i << 10));
    }
    for (int k = s; k < cnt; k += 4) {
        const float4 vv = *(const float4*)(xwb + (size_t)(unsigned)s_off[k]);
        acc.x += vv.x; acc.y += vv.y; acc.z += vv.z; acc.w += vv.w;
    }
    s_red[s][c] = acc;
    __syncthreads();
    if (s == 0) {
        float4 a0 = s_red[0][c];
        float4 a1 = s_red[1][c];
        float4 a2 = s_red[2][c];
        float4 a3 = s_red[3][c];
        const float di = g_dinv[i];
        float4 r;
        r.x = di * (((a0.x + a1.x) + a2.x) + a3.x);
        r.y = di * (((a0.y + a1.y) + a2.y) + a3.y);
        r.z = di * (((a0.z + a1.z) + a2.z) + a3.z);
        r.w = di * (((a0.w + a1.w) + a2.w) + a3.w);
        *(float4*)&out[(size_t)i * 256 + c * 4] = r;
    }
}

// ---------------------------------------------------------------- launch
extern "C" void kernel_launch(void* const* d_in, const int* in_sizes, int n_in,
                              void* d_out, int out_size) {
    const float* x   = (const float*)d_in[0];
    const int*   ei  = (const int*)d_in[1];
    const float* w   = (const float*)d_in[2];
    float*       out = (float*)d_out;
    const int E = in_sizes[1] / 2;

    zero_bitmap_kernel<<<1024, 256>>>();
    scatter_kernel<<<(E + 255) / 256, 256>>>(ei, E);
    degree_kernel<<<(N_NODES + 7) / 8, 256>>>();
    gemm_kernel<<<dim3(256 / 64, (N_NODES + 63) / 64), 256>>>(x, w);
    spmm_kernel<<<N_NODES, 256>>>(out);
}

// round 6
// speedup vs baseline: 1.2156x; 1.0447x over previous
#include <cuda_runtime.h>
#include <stdint.h>

#define N_NODES 10000
#define ROW_WORDS 320      // 313 words used (10016 bits), padded to 320 for alignment
#define USED_WORDS 313
#define D 256
#define MAX_NBR 1024

// Scratch (allocation-free rule: __device__ globals)
__device__ uint32_t g_bitmap[(size_t)N_NODES * ROW_WORDS];   // 12.8 MB
__device__ float    g_dinv[N_NODES];
__device__ float    g_xw[(size_t)N_NODES * D];               // dinv[j] * (x[j] @ W)

// ---------------------------------------------------------------- zero bitmap
__global__ void zero_bitmap_kernel() {
    const size_t total = (size_t)N_NODES * ROW_WORDS / 4;   // uint4 count
    uint4* p = (uint4*)g_bitmap;
    uint4 z = make_uint4(0u, 0u, 0u, 0u);
    for (size_t i = (size_t)blockIdx.x * blockDim.x + threadIdx.x; i < total;
         i += (size_t)gridDim.x * blockDim.x)
        p[i] = z;
}

// ------------------------------------------------------------- edge scatter
// edge_index is int32 [2, E].
__global__ void scatter_kernel(const int* __restrict__ ei, int E) {
    int e = blockIdx.x * blockDim.x + threadIdx.x;
    if (e >= E) return;
    int s = ei[e];
    int d = ei[E + e];
    if ((unsigned)s >= N_NODES || (unsigned)d >= N_NODES) return;  // defensive
    atomicOr(&g_bitmap[(size_t)s * ROW_WORDS + (d >> 5)], 1u << (d & 31));
    atomicOr(&g_bitmap[(size_t)d * ROW_WORDS + (s >> 5)], 1u << (s & 31));
}

// ------------------------------------------------------ degree -> dinv
__global__ void degree_kernel() {
    int i = blockIdx.x * (blockDim.x >> 5) + (threadIdx.x >> 5);
    if (i >= N_NODES) return;
    int lane = threadIdx.x & 31;
    const uint32_t* row = g_bitmap + (size_t)i * ROW_WORDS;
    int s = 0;
    for (int w = lane; w < USED_WORDS; w += 32) s += __popc(row[w]);
    #pragma unroll
    for (int o = 16; o; o >>= 1) s += __shfl_down_sync(0xffffffffu, s, o);
    if (lane == 0) g_dinv[i] = rsqrtf((float)s + 1.0f);
}

// ------------------------------------------------------ GEMM: xw = dinv .* (x @ W)
// 128x64 CTA tile, BK=16, 256 threads, 8x4 microtile.
// Per kk: 3x LDS.128 -> 32 FFMA (vs 2:16 before) — lifts the LSU bound.
// Epilogue scales each output row m by dinv[m].
__global__ __launch_bounds__(256) void gemm_kernel(const float* __restrict__ A,
                                                   const float* __restrict__ W) {
    const int n0 = blockIdx.x * 64;
    const int m0 = blockIdx.y * 128;
    __shared__ float As[16][128];   // As[k][m]
    __shared__ float Bs[16][64];    // Bs[k][n]
    const int t = threadIdx.x;
    const int tx = t & 15;          // N dim: 16 threads x TN=4 = 64 cols
    const int ty = t >> 4;          // M dim: 16 threads x TM=8 = 128 rows

    float acc[8][4];
    #pragma unroll
    for (int r = 0; r < 8; r++)
        #pragma unroll
        for (int c = 0; c < 4; c++) acc[r][c] = 0.f;

    const int am  = t >> 2;         // A loader: rows am and am+64
    const int akq = (t & 3) * 4;    //           k quad
    const int bk  = t >> 4;         // B loader
    const int bnq = (t & 15) * 4;

    for (int k0 = 0; k0 < 256; k0 += 16) {
        #pragma unroll
        for (int half = 0; half < 2; half++) {
            int arow = m0 + am + half * 64;
            float4 av = make_float4(0.f, 0.f, 0.f, 0.f);
            if (arow < N_NODES)
                av = *(const float4*)&A[(size_t)arow * 256 + k0 + akq];
            As[akq + 0][am + half * 64] = av.x;
            As[akq + 1][am + half * 64] = av.y;
            As[akq + 2][am + half * 64] = av.z;
            As[akq + 3][am + half * 64] = av.w;
        }
        *(float4*)&Bs[bk][bnq] = *(const float4*)&W[(size_t)(k0 + bk) * 256 + n0 + bnq];
        __syncthreads();
        #pragma unroll
        for (int kk = 0; kk < 16; kk++) {
            float4 a0 = *(const float4*)&As[kk][ty * 8];
            float4 a1 = *(const float4*)&As[kk][ty * 8 + 4];
            float4 b  = *(const float4*)&Bs[kk][tx * 4];
            acc[0][0] += a0.x * b.x; acc[0][1] += a0.x * b.y; acc[0][2] += a0.x * b.z; acc[0][3] += a0.x * b.w;
            acc[1][0] += a0.y * b.x; acc[1][1] += a0.y * b.y; acc[1][2] += a0.y * b.z; acc[1][3] += a0.y * b.w;
            acc[2][0] += a0.z * b.x; acc[2][1] += a0.z * b.y; acc[2][2] += a0.z * b.z; acc[2][3] += a0.z * b.w;
            acc[3][0] += a0.w * b.x; acc[3][1] += a0.w * b.y; acc[3][2] += a0.w * b.z; acc[3][3] += a0.w * b.w;
            acc[4][0] += a1.x * b.x; acc[4][1] += a1.x * b.y; acc[4][2] += a1.x * b.z; acc[4][3] += a1.x * b.w;
            acc[5][0] += a1.y * b.x; acc[5][1] += a1.y * b.y; acc[5][2] += a1.y * b.z; acc[5][3] += a1.y * b.w;
            acc[6][0] += a1.z * b.x; acc[6][1] += a1.z * b.y; acc[6][2] += a1.z * b.z; acc[6][3] += a1.z * b.w;
            acc[7][0] += a1.w * b.x; acc[7][1] += a1.w * b.y; acc[7][2] += a1.w * b.z; acc[7][3] += a1.w * b.w;
        }
        __syncthreads();
    }
    #pragma unroll
    for (int r = 0; r < 8; r++) {
        int m = m0 + ty * 8 + r;
        if (m < N_NODES) {
            float dv = g_dinv[m];
            *(float4*)&g_xw[(size_t)m * 256 + n0 + tx * 4] =
                make_float4(dv * acc[r][0], dv * acc[r][1],
                            dv * acc[r][2], dv * acc[r][3]);
        }
    }
}

// ------------------------------------------------------ SpMM: out = A_norm @ xw'
// One CTA (256 threads) per row i.
// Phase 1: deterministic neighbor extraction (count -> scan -> ordered write of
//          precomputed BYTE offsets j*1024).
// Phase 2: vectorized gather-sum. Thread layout: c = t&63 owns columns
//          [4c,4c+4) as a float4; s = t>>6 handles neighbors k ≡ s (mod 4).
//          Fixed-order shared reduction over the 4 slices -> deterministic.
__global__ __launch_bounds__(256) void spmm_kernel(float* __restrict__ out) {
    const int i = blockIdx.x;
    const int t = threadIdx.x;
    __shared__ int    s_off[MAX_NBR];     // byte offsets (j << 10)
    __shared__ int    s_warp_tot[8];
    __shared__ int    s_cnt;
    __shared__ float4 s_red[4][64];

    const uint32_t* row = g_bitmap + (size_t)i * ROW_WORDS;

    // thread t owns words {t, t+256} (t+256 only if t<64); padding words are zero
    uint32_t w0 = row[t];
    uint32_t w1 = (t < ROW_WORDS - 256) ? row[t + 256] : 0u;
    int cnt_local = __popc(w0) + __popc(w1);

    // block exclusive scan of cnt_local (deterministic ordering)
    int lane = t & 31, wid = t >> 5;
    int v = cnt_local;
    #pragma unroll
    for (int o = 1; o < 32; o <<= 1) {
        int u = __shfl_up_sync(0xffffffffu, v, o);
        if (lane >= o) v += u;
    }
    if (lane == 31) s_warp_tot[wid] = v;
    __syncthreads();
    int base = 0;
    for (int ww = 0; ww < wid; ww++) base += s_warp_tot[ww];
    int offset = base + v - cnt_local;   // exclusive prefix for this thread
    if (t == 0) {
        int tot = 0;
        #pragma unroll
        for (int ww = 0; ww < 8; ww++) tot += s_warp_tot[ww];
        s_cnt = tot;
    }
    // write this thread's bits as byte offsets (word t first, then word t+256)
    {
        uint32_t bits = w0;
        int wbase = t * 32;
        while (bits) {
            int b = __ffs(bits) - 1;
            bits &= bits - 1;
            if (offset < MAX_NBR) s_off[offset] = (wbase + b) << 10;
            offset++;
        }
        bits = w1;
        wbase = (t + 256) * 32;
        while (bits) {
            int b = __ffs(bits) - 1;
            bits &= bits - 1;
            if (offset < MAX_NBR) s_off[offset] = (wbase + b) << 10;
            offset++;
        }
    }
    __syncthreads();
    const int cnt = min(s_cnt, MAX_NBR);

    const int c = t & 63;        // column group: float4 at cols [4c, 4c+4)
    const int s = t >> 6;        // neighbor slice
    const char* xwb = (const char*)g_xw + (size_t)c * 16;

    float4 acc = make_float4(0.f, 0.f, 0.f, 0.f);
    if (s == 0) {
        // +I self term: xw row i (already dinv[i]-scaled)
        acc = *(const float4*)(xwb + ((size_t)i << 10));
    }
    for (int k = s; k < cnt; k += 4) {
        const float4 vv = *(const float4*)(xwb + (size_t)(unsigned)s_off[k]);
        acc.x += vv.x; acc.y += vv.y; acc.z += vv.z; acc.w += vv.w;
    }
    s_red[s][c] = acc;
    __syncthreads();
    if (s == 0) {
        float4 a0 = s_red[0][c];
        float4 a1 = s_red[1][c];
        float4 a2 = s_red[2][c];
        float4 a3 = s_red[3][c];
        const float di = g_dinv[i];
        float4 r;
        r.x = di * (((a0.x + a1.x) + a2.x) + a3.x);
        r.y = di * (((a0.y + a1.y) + a2.y) + a3.y);
        r.z = di * (((a0.z + a1.z) + a2.z) + a3.z);
        r.w = di * (((a0.w + a1.w) + a2.w) + a3.w);
        *(float4*)&out[(size_t)i * 256 + c * 4] = r;
    }
}

// ---------------------------------------------------------------- launch
extern "C" void kernel_launch(void* const* d_in, const int* in_sizes, int n_in,
                              void* d_out, int out_size) {
    const float* x   = (const float*)d_in[0];
    const int*   ei  = (const int*)d_in[1];
    const float* w   = (const float*)d_in[2];
    float*       out = (float*)d_out;
    const int E = in_sizes[1] / 2;

    zero_bitmap_kernel<<<1024, 256>>>();
    scatter_kernel<<<(E + 255) / 256, 256>>>(ei, E);
    degree_kernel<<<(N_NODES + 7) / 8, 256>>>();
    gemm_kernel<<<dim3(256 / 64, (N_NODES + 127) / 128), 256>>>(x, w);
    spmm_kernel<<<N_NODES, 256>>>(out);
}

// round 9
// speedup vs baseline: 1.3939x; 1.1467x over previous
#include <cuda_runtime.h>
#include <cuda_bf16.h>
#include <stdint.h>

#define N_NODES 10000
#define M_TILES 79
#define M_PAD   (M_TILES * 128)     // 10112
#define ROW_WORDS 320
#define USED_WORDS 313
#define D 256
#define MAX_NBR 1024

#define KTOT 768                    // [hi | lo | hi] logical K
#define NSTEP 12                    // KTOT / 64
#define SROW_B 144                  // padded smem row: 72 bf16 = 144 bytes
#define STILE  (128 * SROW_B)       // 18432 bytes per tile buffer
#define GEMM_SMEM (4 * STILE)       // A0,A1,B0,B1 = 73728

// Scratch (allocation-free rule: __device__ globals)
__device__ uint32_t       g_bitmap[(size_t)N_NODES * ROW_WORDS];   // 12.8 MB
__device__ float          g_dinv[N_NODES];
__device__ float          g_xw[(size_t)N_NODES * D];
__device__ __nv_bfloat16  g_abf[(size_t)M_PAD * KTOT];             // [m, hi|lo|hi]
__device__ __nv_bfloat16  g_bbf[(size_t)256 * KTOT];               // W^T: [n, hi|hi|lo]

__device__ __forceinline__ uint32_t smem_u32(const void* p) {
    uint32_t a;
    asm("{ .reg .u64 t; cvta.to.shared.u64 t, %1; cvt.u32.u64 %0, t; }" : "=r"(a) : "l"(p));
    return a;
}
__device__ __forceinline__ void cp_async16(uint32_t dst, const void* src) {
    asm volatile("cp.async.cg.shared.global [%0], [%1], 16;" :: "r"(dst), "l"(src));
}
__device__ __forceinline__ void ldsm_x4(uint32_t& r0, uint32_t& r1, uint32_t& r2,
                                        uint32_t& r3, uint32_t addr) {
    asm volatile("ldmatrix.sync.aligned.m8n8.x4.shared.b16 {%0,%1,%2,%3}, [%4];"
                 : "=r"(r0), "=r"(r1), "=r"(r2), "=r"(r3) : "r"(addr));
}
#define MMA16816(d, a, b)                                                       \
    asm volatile("mma.sync.aligned.m16n8k16.row.col.f32.bf16.bf16.f32 "         \
                 "{%0,%1,%2,%3}, {%4,%5,%6,%7}, {%8,%9}, {%0,%1,%2,%3};"        \
                 : "+f"((d)[0]), "+f"((d)[1]), "+f"((d)[2]), "+f"((d)[3])       \
                 : "r"((a)[0]), "r"((a)[1]), "r"((a)[2]), "r"((a)[3]),          \
                   "r"((b)[0]), "r"((b)[1]))

// ---------------------------------------------------------------- zero bitmap
__global__ void zero_bitmap_kernel() {
    const size_t total = (size_t)N_NODES * ROW_WORDS / 4;
    uint4* p = (uint4*)g_bitmap;
    uint4 z = make_uint4(0u, 0u, 0u, 0u);
    for (size_t i = (size_t)blockIdx.x * blockDim.x + threadIdx.x; i < total;
         i += (size_t)gridDim.x * blockDim.x)
        p[i] = z;
}

// ------------------------------------------------------------- edge scatter
__global__ void scatter_kernel(const int* __restrict__ ei, int E) {
    int e = blockIdx.x * blockDim.x + threadIdx.x;
    if (e >= E) return;
    int s = ei[e];
    int d = ei[E + e];
    if ((unsigned)s >= N_NODES || (unsigned)d >= N_NODES) return;
    atomicOr(&g_bitmap[(size_t)s * ROW_WORDS + (d >> 5)], 1u << (d & 31));
    atomicOr(&g_bitmap[(size_t)d * ROW_WORDS + (s >> 5)], 1u << (s & 31));
}

// ------------------------------------------------------ degree -> dinv
__global__ void degree_kernel() {
    int i = blockIdx.x * (blockDim.x >> 5) + (threadIdx.x >> 5);
    if (i >= N_NODES) return;
    int lane = threadIdx.x & 31;
    const uint32_t* row = g_bitmap + (size_t)i * ROW_WORDS;
    int s = 0;
    for (int w = lane; w < USED_WORDS; w += 32) s += __popc(row[w]);
    #pragma unroll
    for (int o = 16; o; o >>= 1) s += __shfl_down_sync(0xffffffffu, s, o);
    if (lane == 0) g_dinv[i] = rsqrtf((float)s + 1.0f);
}

// ------------------------------------------------- bf16 hi/lo conversions
// A' row: [hi(256) | lo(256) | hi(256)]
__global__ void convert_x_kernel(const float* __restrict__ x) {
    int idx = blockIdx.x * blockDim.x + threadIdx.x;
    if (idx >= M_PAD * D) return;
    int i = idx >> 8, k = idx & 255;
    float a = (i < N_NODES) ? x[(size_t)i * D + k] : 0.f;
    __nv_bfloat16 hi = __float2bfloat16(a);
    __nv_bfloat16 lo = __float2bfloat16(a - __bfloat162float(hi));
    __nv_bfloat16* r = g_abf + (size_t)i * KTOT;
    r[k]       = hi;
    r[256 + k] = lo;
    r[512 + k] = hi;
}
// B' row (W^T): [hi(256) | hi(256) | lo(256)]
__global__ void convert_w_kernel(const float* __restrict__ W) {
    int idx = blockIdx.x * blockDim.x + threadIdx.x;
    if (idx >= 256 * 256) return;
    int n = idx >> 8, k = idx & 255;
    float a = W[(size_t)k * 256 + n];            // transpose -> [n, k]
    __nv_bfloat16 hi = __float2bfloat16(a);
    __nv_bfloat16 lo = __float2bfloat16(a - __bfloat162float(hi));
    __nv_bfloat16* r = g_bbf + (size_t)n * KTOT;
    r[k]       = hi;
    r[256 + k] = hi;
    r[512 + k] = lo;
}

// ---------------------- mma.sync bf16 GEMM: xw = dinv .* (x @ W), compensated
// CTA 128x128, BK=64, 8 warps (warp tile 32x64), cp.async double buffer.
__global__ __launch_bounds__(256) void gemm_mma_kernel() {
    extern __shared__ char smem[];
    const uint32_t sb = smem_u32(smem);
    const int t = threadIdx.x;
    const int lane = t & 31, wid = t >> 5;
    const int m0 = blockIdx.y * 128;
    const int n0 = blockIdx.x * 128;
    const int m_off = (wid >> 1) * 32;
    const int n_off = (wid & 1) * 64;

    float acc[2][8][4];
    #pragma unroll
    for (int mi = 0; mi < 2; mi++)
        #pragma unroll
        for (int ni = 0; ni < 8; ni++)
            #pragma unroll
            for (int q = 0; q < 4; q++) acc[mi][ni][q] = 0.f;

    // fill buffers: A at sb + buf*STILE, B at sb + 2*STILE + buf*STILE
    const int frow = t >> 1;                 // 0..127
    const int fq   = (t & 1) * 4;            // two 16B chunks per row half... see loop
    (void)frow; (void)fq;

    auto fill = [&](int s, int buf) {
        const char* asrc = (const char*)g_abf + (size_t)m0 * (KTOT * 2) + s * 128;
        const char* bsrc = (const char*)g_bbf + (size_t)n0 * (KTOT * 2) + s * 128;
        uint32_t adst = sb + buf * STILE;
        uint32_t bdst = sb + 2 * STILE + buf * STILE;
        #pragma unroll
        for (int it = 0; it < 4; it++) {
            int idx = t + it * 256;          // 0..1023
            int row = idx >> 3, q = idx & 7; // 128 rows x 8 chunks of 16B
            uint32_t so = row * SROW_B + q * 16;
            size_t go = (size_t)row * (KTOT * 2) + q * 16;
            cp_async16(adst + so, asrc + go);
            cp_async16(bdst + so, bsrc + go);
        }
        asm volatile("cp.async.commit_group;" ::: "memory");
    };

    auto compute = [&](int buf) {
        uint32_t abase = sb + buf * STILE;
        uint32_t bbase = sb + 2 * STILE + buf * STILE;
        #pragma unroll
        for (int kk = 0; kk < 4; kk++) {
            uint32_t a[2][4];
            #pragma unroll
            for (int mi = 0; mi < 2; mi++) {
                uint32_t row = m_off + mi * 16 + (lane & 15);
                uint32_t addr = abase + row * SROW_B + kk * 32 + ((lane >> 4) * 16);
                ldsm_x4(a[mi][0], a[mi][1], a[mi][2], a[mi][3], addr);
            }
            uint32_t b[8][2];
            #pragma unroll
            for (int p = 0; p < 4; p++) {
                uint32_t row = n_off + p * 16 + (lane & 7) + ((lane >> 4) << 3);
                uint32_t addr = bbase + row * SROW_B + kk * 32 + (((lane >> 3) & 1) * 16);
                uint32_t r0, r1, r2, r3;
                ldsm_x4(r0, r1, r2, r3, addr);
                b[2 * p][0] = r0; b[2 * p][1] = r1;
                b[2 * p + 1][0] = r2; b[2 * p + 1][1] = r3;
            }
            #pragma unroll
            for (int mi = 0; mi < 2; mi++)
                #pragma unroll
                for (int ni = 0; ni < 8; ni++)
                    MMA16816(acc[mi][ni], a[mi], b[ni]);
        }
    };

    fill(0, 0);
    for (int s = 0; s < NSTEP; s++) {
        const int buf = s & 1;
        if (s + 1 < NSTEP) {
            fill(s + 1, buf ^ 1);
            asm volatile("cp.async.wait_group 1;" ::: "memory");
        } else {
            asm volatile("cp.async.wait_group 0;" ::: "memory");
        }
        __syncthreads();
        compute(buf);
        __syncthreads();
    }

    // Epilogue: d-frag -> dinv-scaled fp32 g_xw
    const int gid = lane >> 2, t4 = lane & 3;
    #pragma unroll
    for (int mi = 0; mi < 2; mi++) {
        int r0 = m0 + m_off + mi * 16 + gid;
        int r1 = r0 + 8;
        float dv0 = (r0 < N_NODES) ? g_dinv[r0] : 0.f;
        float dv1 = (r1 < N_NODES) ? g_dinv[r1] : 0.f;
        #pragma unroll
        for (int ni = 0; ni < 8; ni++) {
            int col = n0 + n_off + ni * 8 + t4 * 2;
            if (r0 < N_NODES)
                *(float2*)&g_xw[(size_t)r0 * 256 + col] =
                    make_float2(dv0 * acc[mi][ni][0], dv0 * acc[mi][ni][1]);
            if (r1 < N_NODES)
                *(float2*)&g_xw[(size_t)r1 * 256 + col] =
                    make_float2(dv1 * acc[mi][ni][2], dv1 * acc[mi][ni][3]);
        }
    }
}

// ------------------------------------------------------ SpMM: out = A_norm @ xw'
__global__ __launch_bounds__(256) void spmm_kernel(float* __restrict__ out) {
    const int i = blockIdx.x;
    const int t = threadIdx.x;
    __shared__ int    s_off[MAX_NBR];
    __shared__ int    s_warp_tot[8];
    __shared__ int    s_cnt;
    __shared__ float4 s_red[4][64];

    const uint32_t* row = g_bitmap + (size_t)i * ROW_WORDS;
    uint32_t w0 = row[t];
    uint32_t w1 = (t < ROW_WORDS - 256) ? row[t + 256] : 0u;
    int cnt_local = __popc(w0) + __popc(w1);

    int lane = t & 31, wid = t >> 5;
    int v = cnt_local;
    #pragma unroll
    for (int o = 1; o < 32; o <<= 1) {
        int u = __shfl_up_sync(0xffffffffu, v, o);
        if (lane >= o) v += u;
    }
    if (lane == 31) s_warp_tot[wid] = v;
    __syncthreads();
    int base = 0;
    for (int ww = 0; ww < wid; ww++) base += s_warp_tot[ww];
    int offset = base + v - cnt_local;
    if (t == 0) {
        int tot = 0;
        #pragma unroll
        for (int ww = 0; ww < 8; ww++) tot += s_warp_tot[ww];
        s_cnt = tot;
    }
    {
        uint32_t bits = w0;
        int wbase = t * 32;
        while (bits) {
            int b = __ffs(bits) - 1;
            bits &= bits - 1;
            if (offset < MAX_NBR) s_off[offset] = (wbase + b) << 10;
            offset++;
        }
        bits = w1;
        wbase = (t + 256) * 32;
        while (bits) {
            int b = __ffs(bits) - 1;
            bits &= bits - 1;
            if (offset < MAX_NBR) s_off[offset] = (wbase + b) << 10;
            offset++;
        }
    }
    __syncthreads();
    const int cnt = min(s_cnt, MAX_NBR);

    const int c = t & 63;
    const int s = t >> 6;
    const char* xwb = (const char*)g_xw + (size_t)c * 16;

    float4 acc = make_float4(0.f, 0.f, 0.f, 0.f);
    if (s == 0) acc = *(const float4*)(xwb + ((size_t)i << 10));   // +I self term
    for (int k = s; k < cnt; k += 4) {
        const float4 vv = *(const float4*)(xwb + (size_t)(unsigned)s_off[k]);
        acc.x += vv.x; acc.y += vv.y; acc.z += vv.z; acc.w += vv.w;
    }
    s_red[s][c] = acc;
    __syncthreads();
    if (s == 0) {
        float4 a0 = s_red[0][c];
        float4 a1 = s_red[1][c];
        float4 a2 = s_red[2][c];
        float4 a3 = s_red[3][c];
        const float di = g_dinv[i];
        float4 r;
        r.x = di * (((a0.x + a1.x) + a2.x) + a3.x);
        r.y = di * (((a0.y + a1.y) + a2.y) + a3.y);
        r.z = di * (((a0.z + a1.z) + a2.z) + a3.z);
        r.w = di * (((a0.w + a1.w) + a2.w) + a3.w);
        *(float4*)&out[(size_t)i * 256 + c * 4] = r;
    }
}

// ---------------------------------------------------------------- launch
extern "C" void kernel_launch(void* const* d_in, const int* in_sizes, int n_in,
                              void* d_out, int out_size) {
    const float* x   = (const float*)d_in[0];
    const int*   ei  = (const int*)d_in[1];
    const float* w   = (const float*)d_in[2];
    float*       out = (float*)d_out;
    const int E = in_sizes[1] / 2;

    cudaFuncSetAttribute(gemm_mma_kernel,
                         cudaFuncAttributeMaxDynamicSharedMemorySize, GEMM_SMEM);

    zero_bitmap_kernel<<<1024, 256>>>();
    scatter_kernel<<<(E + 255) / 256, 256>>>(ei, E);
    degree_kernel<<<(N_NODES + 7) / 8, 256>>>();
    convert_x_kernel<<<(M_PAD * D + 255) / 256, 256>>>(x);
    convert_w_kernel<<<(256 * 256 + 255) / 256, 256>>>(w);
    gemm_mma_kernel<<<dim3(2, M_TILES), 256, GEMM_SMEM>>>();
    spmm_kernel<<<N_NODES, 256>>>(out);
}